// round 2
// baseline (speedup 1.0000x reference)
#include <cuda_runtime.h>
#include <cstdint>

#define BATCH   8
#define NPTS    8192
#define DIM     64
#define SPTS    1024      // NPOINT
#define NS      32        // NSAMPLE
#define MROWS   (BATCH*SPTS*NS)   // 262144

// ---------------- scratch (device globals; no allocation allowed) ----------
__device__ int   g_fps_idx[BATCH*SPTS];
__device__ float g_new_xyz[BATCH*SPTS*3];
__device__ int   g_ball[BATCH*SPTS*NS];
__device__ float g_ptsT[BATCH*NPTS*DIM];          // 16 MB
__device__ float g_feat[(size_t)MROWS*68];        // 71 MB (col 67 zero pad)
__device__ float g_h1[(size_t)MROWS*64];          // 64 MB
__device__ float g_h2[(size_t)MROWS*64];          // 64 MB
__device__ float g_h3[(size_t)MROWS*128];         // 128 MB
__device__ float g_part[2*1024*128];
__device__ float g_scale[128];
__device__ float g_shift[128];

// ---------------- FPS: 1 block per batch, points register-resident ---------
__global__ __launch_bounds__(1024,1) void fps_kernel(const float* __restrict__ xyz){
  extern __shared__ float sxyz[];            // 3*8192 floats
  __shared__ float bc[3];
  __shared__ unsigned long long swarp[32];
  const int b   = blockIdx.x;
  const int tid = threadIdx.x;
  const float* xb = xyz + (size_t)b*3*NPTS;
  for (int i=tid; i<3*NPTS; i+=1024) sxyz[i]=xb[i];
  __syncthreads();

  float rx[8],ry[8],rz[8],rd[8];
#pragma unroll
  for (int i=0;i<8;i++){
    int p = i*1024+tid;
    rx[i]=sxyz[p]; ry[i]=sxyz[NPTS+p]; rz[i]=sxyz[2*NPTS+p];
    rd[i]=1e10f;
  }
  int far=0;
  const int lane=tid&31, wid=tid>>5;
  const unsigned base = (unsigned)(NPTS-1-tid);

  for (int it=0; it<SPTS; ++it){
    if (tid==0){
      g_fps_idx[b*SPTS+it]=far;
      bc[0]=sxyz[far]; bc[1]=sxyz[NPTS+far]; bc[2]=sxyz[2*NPTS+far];
    }
    __syncthreads();
    const float cx=bc[0], cy=bc[1], cz=bc[2];
    unsigned long long best=0ull;
#pragma unroll
    for (int i=0;i<8;i++){
      float dx=__fsub_rn(rx[i],cx);
      float dy=__fsub_rn(ry[i],cy);
      float dz=__fsub_rn(rz[i],cz);
      // exact ((dx^2+dy^2)+dz^2), no FMA contraction (index decisions!)
      float d=__fadd_rn(__fadd_rn(__fmul_rn(dx,dx),__fmul_rn(dy,dy)),__fmul_rn(dz,dz));
      float nd=fminf(rd[i],d);
      rd[i]=nd;
      // key: value-major, then smaller index wins (first-occurrence argmax)
      unsigned long long key=((unsigned long long)__float_as_uint(nd)<<32)
                            |(unsigned long long)(base-(unsigned)(i<<10));
      best = (key>best)?key:best;
    }
#pragma unroll
    for (int o=16;o>0;o>>=1){
      unsigned long long oth=__shfl_xor_sync(0xffffffffu,best,o);
      best = (oth>best)?oth:best;
    }
    if (lane==0) swarp[wid]=best;
    __syncthreads();
    if (wid==0){
      unsigned long long k2=swarp[lane];
#pragma unroll
      for (int o=16;o>0;o>>=1){
        unsigned long long oth=__shfl_xor_sync(0xffffffffu,k2,o);
        k2 = (oth>k2)?oth:k2;
      }
      if (lane==0) far = (NPTS-1) - (int)(unsigned)(k2 & 0xffffffffull);
    }
  }
}

// ---------------- new_xyz gather + first output section --------------------
__global__ void newxyz_kernel(const float* __restrict__ xyz, float* __restrict__ out){
  int b=blockIdx.x, s=threadIdx.x;
  int idx = g_fps_idx[b*SPTS+s];
#pragma unroll
  for (int d=0; d<3; d++){
    float v = xyz[(size_t)b*3*NPTS + (size_t)d*NPTS + idx];
    g_new_xyz[(b*SPTS+s)*3+d]=v;
    out[(size_t)b*3*SPTS + (size_t)d*SPTS + s]=v;
  }
}

// ---------------- ball query: one warp per query ---------------------------
__global__ void ball_kernel(const float* __restrict__ xyz){
  const int gw   = (blockIdx.x*blockDim.x + threadIdx.x) >> 5;  // 0..8191
  const int lane = threadIdx.x & 31;
  const int wl   = threadIdx.x >> 5;
  const int b = gw >> 10;
  __shared__ int sidx[8][NS];
  const float cx=g_new_xyz[gw*3+0], cy=g_new_xyz[gw*3+1], cz=g_new_xyz[gw*3+2];
  const float* xb = xyz + (size_t)b*3*NPTS;
  unsigned cnt=0;
  for (int basep=0; basep<NPTS; basep+=32){
    int p = basep+lane;
    float dx=__fsub_rn(cx,xb[p]);
    float dy=__fsub_rn(cy,xb[NPTS+p]);
    float dz=__fsub_rn(cz,xb[2*NPTS+p]);
    float d=__fadd_rn(__fadd_rn(__fmul_rn(dx,dx),__fmul_rn(dy,dy)),__fmul_rn(dz,dz));
    bool in = !(d > 0.04f);                   // matches float32(0.2*0.2 f64)
    unsigned m = __ballot_sync(0xffffffffu, in);
    if (in){
      unsigned r = cnt + __popc(m & ((1u<<lane)-1u));
      if (r < NS) sidx[wl][r] = p;
    }
    cnt += __popc(m);
    if (cnt >= NS) break;
  }
  __syncwarp();
  unsigned c = cnt < NS ? cnt : NS;           // c >= 1 (self point always in)
  int first = sidx[wl][0];
  int v = (lane < (int)c) ? sidx[wl][lane] : first;
  g_ball[gw*NS + lane] = v;
}

// ---------------- points transpose (B,64,N) -> (B,N,64) --------------------
__global__ void transpose_kernel(const float* __restrict__ pts){
  __shared__ float tile[32][33];
  int b  = blockIdx.z;
  int n0 = blockIdx.x*32;
  int c0 = blockIdx.y*32;
  int tx = threadIdx.x, ty = threadIdx.y;     // 32 x 8
  const float* pb = pts + (size_t)b*DIM*NPTS;
#pragma unroll
  for (int j=0;j<32;j+=8)
    tile[ty+j][tx] = pb[(size_t)(c0+ty+j)*NPTS + n0+tx];
  __syncthreads();
  float* ob = g_ptsT + (size_t)b*NPTS*DIM;
#pragma unroll
  for (int j=0;j<32;j+=8)
    ob[(size_t)(n0+ty+j)*DIM + c0+tx] = tile[tx][ty+j];
}

// ---------------- build feat [M][68]: norm(3) | pts(64) | 0 ----------------
__global__ void feat_kernel(const float* __restrict__ xyz){
  const int blk = blockIdx.x;                 // b*1024+s
  const int b   = blk >> 10;
  __shared__ int   sn[NS];
  __shared__ float sc[3];
  const int tid = threadIdx.x;
  if (tid<NS) sn[tid]=g_ball[blk*NS+tid];
  if (tid>=32 && tid<35) sc[tid-32]=g_new_xyz[blk*3 + (tid-32)];
  __syncthreads();
  const int c  = tid & 63;
  const int k0 = tid >> 6;
  const size_t mbase = (size_t)blk*NS;
#pragma unroll
  for (int k=k0; k<NS; k+=4){
    int n = sn[k];
    g_feat[(mbase+k)*68 + 3 + c] = g_ptsT[((size_t)b*NPTS + n)*DIM + c];
  }
  if (tid<96){
    int k=tid/3, d=tid%3;
    int n=sn[k];
    g_feat[(mbase+k)*68 + d] =
      __fsub_rn(xyz[(size_t)b*3*NPTS + (size_t)d*NPTS + n], sc[d]);
  }
  if (tid<NS) g_feat[(mbase+tid)*68 + 67] = 0.f;
}

// ---------------- GEMM: h = act(A) @ W^T + bias ----------------------------
// A: [M][K] (K=68 padded or 64), W: [BN][wld] row-major, H: [M][BN]
// AFF: apply y = relu(v*scale[c]+shift[c]) while loading A (prev layer BN+ReLU)
template<int K, int BN, bool AFF>
__global__ __launch_bounds__(256) void gemm_kernel(const float* __restrict__ A,
    const float* __restrict__ W, int wld,
    const float* __restrict__ bias, float* __restrict__ H){
  extern __shared__ float sm[];
  float* sA    = sm;                    // 64*K
  float* sB    = sA + 64*K;             // K*(BN+4), transposed W, padded rows
  float* sbias = sB + K*(BN+4);         // BN
  float* ssc   = sbias + BN;            // K (AFF only)
  float* ssh   = ssc + K;
  const int tid = threadIdx.x;
  const int m0  = blockIdx.x*64;

  for (int o=tid;o<BN;o+=256) sbias[o]=bias[o];
  if (AFF) for (int cc=tid; cc<K; cc+=256){ ssc[cc]=g_scale[cc]; ssh[cc]=g_shift[cc]; }
  for (int idx=tid; idx<BN*wld; idx+=256){
    int o=idx/wld, cc=idx-o*wld;
    sB[cc*(BN+4)+o]=W[idx];
  }
  if (K>wld) for (int o=tid;o<BN;o+=256) sB[(K-1)*(BN+4)+o]=0.f;
  if (AFF) __syncthreads();             // ssc/ssh visible before A transform

  constexpr int K4 = K/4;
  const float4* A4 = (const float4*)A;
  for (int idx=tid; idx<64*K4; idx+=256){
    int m=idx/K4, c4=idx-m*K4;
    float4 v = A4[(size_t)(m0+m)*K4 + c4];
    if (AFF){
      int cc=c4*4;
      v.x = fmaxf(fmaf(v.x, ssc[cc  ], ssh[cc  ]), 0.f);
      v.y = fmaxf(fmaf(v.y, ssc[cc+1], ssh[cc+1]), 0.f);
      v.z = fmaxf(fmaf(v.z, ssc[cc+2], ssh[cc+2]), 0.f);
      v.w = fmaxf(fmaf(v.w, ssc[cc+3], ssh[cc+3]), 0.f);
    }
    *(float4*)&sA[m*K + c4*4] = v;
  }
  __syncthreads();

  constexpr int NPT = BN/16;
  const int tm = tid>>4, tn = tid&15;
  float acc[4][NPT];
#pragma unroll
  for (int i=0;i<4;i++)
#pragma unroll
    for (int j=0;j<NPT;j++) acc[i][j]=sbias[tn*NPT+j];

  const float* Ap = sA + tm*4*K;
  const float* Bp = sB + tn*NPT;
#pragma unroll 4
  for (int k=0;k<K;k++){
    float a0=Ap[k], a1=Ap[K+k], a2=Ap[2*K+k], a3=Ap[3*K+k];
    float bv[NPT];
    const float4* b4 = (const float4*)(Bp + k*(BN+4));
#pragma unroll
    for (int j=0;j<NPT/4;j++){
      float4 t=b4[j];
      bv[4*j]=t.x; bv[4*j+1]=t.y; bv[4*j+2]=t.z; bv[4*j+3]=t.w;
    }
#pragma unroll
    for (int j=0;j<NPT;j++){
      acc[0][j]=fmaf(a0,bv[j],acc[0][j]);
      acc[1][j]=fmaf(a1,bv[j],acc[1][j]);
      acc[2][j]=fmaf(a2,bv[j],acc[2][j]);
      acc[3][j]=fmaf(a3,bv[j],acc[3][j]);
    }
  }
#pragma unroll
  for (int i=0;i<4;i++){
    float* outp = H + (size_t)(m0+tm*4+i)*BN + tn*NPT;
#pragma unroll
    for (int j=0;j<NPT/4;j++){
      float4 t; t.x=acc[i][4*j]; t.y=acc[i][4*j+1]; t.z=acc[i][4*j+2]; t.w=acc[i][4*j+3];
      *(float4*)(outp + 4*j) = t;
    }
  }
}

// ---------------- BN stats: deterministic two-stage -----------------------
template<int C>
__global__ void stats_kernel(const float* __restrict__ H){
  const int c = threadIdx.x;
  const float* p = H + (size_t)blockIdx.x*256*C;
  float s=0.f, ss=0.f;
  for (int r=0;r<256;r++){ float v=p[(size_t)r*C+c]; s+=v; ss+=v*v; }
  g_part[blockIdx.x*128 + c]            = s;
  g_part[1024*128 + blockIdx.x*128 + c] = ss;
}

template<int C>
__global__ void finalize_kernel(const float* __restrict__ g, const float* __restrict__ beta){
  const int c = threadIdx.x;
  float s=0.f, ss=0.f;
  for (int i=0;i<1024;i++){ s+=g_part[i*128+c]; ss+=g_part[1024*128+i*128+c]; }
  const float inv = 1.0f/(float)MROWS;
  float mean = s*inv;
  float var  = ss*inv - mean*mean;
  float rstd = rsqrtf(var + 1e-5f);
  float sc   = rstd*g[c];
  g_scale[c] = sc;
  g_shift[c] = beta[c] - mean*sc;
}

// ---------------- layer-3 norm+relu+maxpool + second output ----------------
__global__ void pool_kernel(float* __restrict__ out){
  const int blk=blockIdx.x;                  // b*1024+s
  const int o  =threadIdx.x;                 // 0..127
  const int b=blk>>10, s=blk&1023;
  const float sc=g_scale[o], sh=g_shift[o];
  const float* p = g_h3 + (size_t)blk*NS*128 + o;
  float m=-3.4e38f;
#pragma unroll 8
  for (int k=0;k<NS;k++) m = fmaxf(m, fmaf(p[(size_t)k*128], sc, sh));
  out[24576 + (size_t)b*128*SPTS + (size_t)o*SPTS + s] = fmaxf(m, 0.f);
}

// ---------------- launch ----------------------------------------------------
extern "C" void kernel_launch(void* const* d_in, const int* in_sizes, int n_in,
                              void* d_out, int out_size){
  (void)in_sizes; (void)n_in; (void)out_size;
  const float* xyz = (const float*)d_in[0];
  const float* pts = (const float*)d_in[1];
  const float* w0  = (const float*)d_in[2];
  const float* b0  = (const float*)d_in[3];
  const float* gg0 = (const float*)d_in[4];
  const float* be0 = (const float*)d_in[5];
  const float* w1  = (const float*)d_in[6];
  const float* b1  = (const float*)d_in[7];
  const float* gg1 = (const float*)d_in[8];
  const float* be1 = (const float*)d_in[9];
  const float* w2  = (const float*)d_in[10];
  const float* b2  = (const float*)d_in[11];
  const float* gg2 = (const float*)d_in[12];
  const float* be2 = (const float*)d_in[13];
  float* out = (float*)d_out;

  cudaFuncSetAttribute(fps_kernel, cudaFuncAttributeMaxDynamicSharedMemorySize, 3*NPTS*4);
  cudaFuncSetAttribute((const void*)gemm_kernel<68,64,false>,
                       cudaFuncAttributeMaxDynamicSharedMemorySize, 36160);
  cudaFuncSetAttribute((const void*)gemm_kernel<64,64,true>,
                       cudaFuncAttributeMaxDynamicSharedMemorySize, 34560);
  cudaFuncSetAttribute((const void*)gemm_kernel<64,128,true>,
                       cudaFuncAttributeMaxDynamicSharedMemorySize, 51200);

  float *pFeat,*pH1,*pH2,*pH3;
  cudaGetSymbolAddress((void**)&pFeat, g_feat);
  cudaGetSymbolAddress((void**)&pH1,   g_h1);
  cudaGetSymbolAddress((void**)&pH2,   g_h2);
  cudaGetSymbolAddress((void**)&pH3,   g_h3);

  fps_kernel<<<BATCH, 1024, 3*NPTS*4>>>(xyz);
  newxyz_kernel<<<BATCH, SPTS>>>(xyz, out);
  ball_kernel<<<1024, 256>>>(xyz);
  transpose_kernel<<<dim3(NPTS/32, DIM/32, BATCH), dim3(32,8)>>>(pts);
  feat_kernel<<<BATCH*SPTS, 256>>>(xyz);

  gemm_kernel<68,64,false><<<MROWS/64, 256, 36160>>>(pFeat, w0, 67, b0, pH1);
  stats_kernel<64><<<1024, 64>>>(pH1);
  finalize_kernel<64><<<1, 64>>>(gg0, be0);

  gemm_kernel<64,64,true><<<MROWS/64, 256, 34560>>>(pH1, w1, 64, b1, pH2);
  stats_kernel<64><<<1024, 64>>>(pH2);
  finalize_kernel<64><<<1, 64>>>(gg1, be1);

  gemm_kernel<64,128,true><<<MROWS/64, 256, 51200>>>(pH2, w2, 64, b2, pH3);
  stats_kernel<128><<<1024, 128>>>(pH3);
  finalize_kernel<128><<<1, 128>>>(gg2, be2);

  pool_kernel<<<BATCH*SPTS, 128>>>(out);
}

// round 3
// speedup vs baseline: 1.1017x; 1.1017x over previous
#include <cuda_runtime.h>
#include <cstdint>

#define BATCH   8
#define NPTS    8192
#define DIM     64
#define SPTS    1024      // NPOINT
#define NS      32        // NSAMPLE
#define MROWS   (BATCH*SPTS*NS)   // 262144
#define NBLK    (MROWS/64)        // 4096 gemm blocks

typedef unsigned long long u64;

// ---------------- f32x2 packed helpers (Blackwell FFMA2 path) --------------
__device__ __forceinline__ u64 pack2(float lo, float hi){
  u64 r; asm("mov.b64 %0,{%1,%2};" : "=l"(r) : "f"(lo), "f"(hi)); return r;
}
__device__ __forceinline__ void unpack2(float& lo, float& hi, u64 p){
  asm("mov.b64 {%0,%1},%2;" : "=f"(lo), "=f"(hi) : "l"(p));
}
__device__ __forceinline__ u64 add2(u64 a, u64 b){
  u64 r; asm("add.rn.f32x2 %0,%1,%2;" : "=l"(r) : "l"(a), "l"(b)); return r;
}
__device__ __forceinline__ u64 mul2(u64 a, u64 b){
  u64 r; asm("mul.rn.f32x2 %0,%1,%2;" : "=l"(r) : "l"(a), "l"(b)); return r;
}
__device__ __forceinline__ void fma2(u64& d, u64 a, u64 b){
  asm("fma.rn.f32x2 %0,%1,%2,%0;" : "+l"(d) : "l"(a), "l"(b));
}

// ---------------- scratch (device globals; no allocation allowed) ----------
__device__ int   g_fps_idx[BATCH*SPTS];
__device__ float g_new_xyz[BATCH*SPTS*3];
__device__ int   g_ball[BATCH*SPTS*NS];
__device__ float g_ptsT[BATCH*NPTS*DIM];          // 16 MB
__device__ float g_feat[(size_t)MROWS*68];        // 71 MB (col 67 zero pad)
__device__ float g_h1[(size_t)MROWS*64];
__device__ float g_h2[(size_t)MROWS*64];
__device__ float g_h3[(size_t)MROWS*128];
__device__ float g_pS [NBLK*128];
__device__ float g_pSS[NBLK*128];
__device__ float g_r1 [2*64*128];
__device__ float g_scale[128];
__device__ float g_shift[128];

// ---------------- FPS: 1 block per batch, f32x2-packed distances -----------
__global__ __launch_bounds__(1024,1) void fps_kernel(const float* __restrict__ xyz){
  extern __shared__ float sxyz[];            // 3*8192 floats
  __shared__ float bc[3];
  __shared__ u64 swarp[32];
  const int b   = blockIdx.x;
  const int tid = threadIdx.x;
  const float* xb = xyz + (size_t)b*3*NPTS;
  for (int i=tid; i<3*NPTS; i+=1024) sxyz[i]=xb[i];
  __syncthreads();

  // pair j: lane-lo = point j*1024+tid, lane-hi = point (j+4)*1024+tid
  u64 rx2[4], ry2[4], rz2[4];
  float rdl[4], rdh[4];
#pragma unroll
  for (int j=0;j<4;j++){
    int plo=j*1024+tid, phi=(j+4)*1024+tid;
    rx2[j]=pack2(sxyz[plo],       sxyz[phi]);
    ry2[j]=pack2(sxyz[NPTS+plo],  sxyz[NPTS+phi]);
    rz2[j]=pack2(sxyz[2*NPTS+plo],sxyz[2*NPTS+phi]);
    rdl[j]=1e10f; rdh[j]=1e10f;
  }
  int far=0;
  const int lane=tid&31, wid=tid>>5;
  const unsigned base = (unsigned)(NPTS-1-tid);

  for (int it=0; it<SPTS; ++it){
    if (tid==0){
      g_fps_idx[b*SPTS+it]=far;
      bc[0]=sxyz[far]; bc[1]=sxyz[NPTS+far]; bc[2]=sxyz[2*NPTS+far];
    }
    __syncthreads();
    // x + (-c) rounds identically to x - c (IEEE)
    const u64 ncx=pack2(-bc[0],-bc[0]);
    const u64 ncy=pack2(-bc[1],-bc[1]);
    const u64 ncz=pack2(-bc[2],-bc[2]);
    u64 best=0ull;
#pragma unroll
    for (int j=0;j<4;j++){
      u64 dx=add2(rx2[j],ncx);
      u64 dy=add2(ry2[j],ncy);
      u64 dz=add2(rz2[j],ncz);
      // exact ((dx^2+dy^2)+dz^2): separate mul + add roundings per lane
      u64 s2=add2(add2(mul2(dx,dx),mul2(dy,dy)),mul2(dz,dz));
      float dl,dh; unpack2(dl,dh,s2);
      float nl=fminf(rdl[j],dl), nh=fminf(rdh[j],dh);
      rdl[j]=nl; rdh[j]=nh;
      // first-occurrence argmax: on tie prefer lane-lo (smaller point index)
      bool ge = (nl >= nh);
      float nds   = ge ? nl : nh;
      unsigned cs = ge ? (base-(unsigned)(j<<10)) : (base-(unsigned)((j+4)<<10));
      u64 key = ((u64)__float_as_uint(nds)<<32) | (u64)cs;
      best = (key>best)?key:best;
    }
#pragma unroll
    for (int o=16;o>0;o>>=1){
      u64 oth=__shfl_xor_sync(0xffffffffu,best,o);
      best = (oth>best)?oth:best;
    }
    if (lane==0) swarp[wid]=best;
    __syncthreads();
    if (wid==0){
      u64 k2=swarp[lane];
#pragma unroll
      for (int o=16;o>0;o>>=1){
        u64 oth=__shfl_xor_sync(0xffffffffu,k2,o);
        k2 = (oth>k2)?oth:k2;
      }
      if (lane==0) far = (NPTS-1) - (int)(unsigned)(k2 & 0xffffffffull);
    }
  }
}

// ---------------- new_xyz gather + first output section --------------------
__global__ void newxyz_kernel(const float* __restrict__ xyz, float* __restrict__ out){
  int b=blockIdx.x, s=threadIdx.x;
  int idx = g_fps_idx[b*SPTS+s];
#pragma unroll
  for (int d=0; d<3; d++){
    float v = xyz[(size_t)b*3*NPTS + (size_t)d*NPTS + idx];
    g_new_xyz[(b*SPTS+s)*3+d]=v;
    out[(size_t)b*3*SPTS + (size_t)d*SPTS + s]=v;
  }
}

// ---------------- ball query: one warp per query ---------------------------
__global__ void ball_kernel(const float* __restrict__ xyz){
  const int gw   = (blockIdx.x*blockDim.x + threadIdx.x) >> 5;  // 0..8191
  const int lane = threadIdx.x & 31;
  const int wl   = threadIdx.x >> 5;
  const int b = gw >> 10;
  __shared__ int sidx[8][NS];
  const float cx=g_new_xyz[gw*3+0], cy=g_new_xyz[gw*3+1], cz=g_new_xyz[gw*3+2];
  const float* xb = xyz + (size_t)b*3*NPTS;
  unsigned cnt=0;
  for (int basep=0; basep<NPTS; basep+=32){
    int p = basep+lane;
    float dx=__fsub_rn(cx,xb[p]);
    float dy=__fsub_rn(cy,xb[NPTS+p]);
    float dz=__fsub_rn(cz,xb[2*NPTS+p]);
    float d=__fadd_rn(__fadd_rn(__fmul_rn(dx,dx),__fmul_rn(dy,dy)),__fmul_rn(dz,dz));
    bool in = !(d > 0.04f);
    unsigned m = __ballot_sync(0xffffffffu, in);
    if (in){
      unsigned r = cnt + __popc(m & ((1u<<lane)-1u));
      if (r < NS) sidx[wl][r] = p;
    }
    cnt += __popc(m);
    if (cnt >= NS) break;
  }
  __syncwarp();
  unsigned c = cnt < NS ? cnt : NS;
  int first = sidx[wl][0];
  int v = (lane < (int)c) ? sidx[wl][lane] : first;
  g_ball[gw*NS + lane] = v;
}

// ---------------- points transpose (B,64,N) -> (B,N,64) --------------------
__global__ void transpose_kernel(const float* __restrict__ pts){
  __shared__ float tile[32][33];
  int b  = blockIdx.z;
  int n0 = blockIdx.x*32;
  int c0 = blockIdx.y*32;
  int tx = threadIdx.x, ty = threadIdx.y;     // 32 x 8
  const float* pb = pts + (size_t)b*DIM*NPTS;
#pragma unroll
  for (int j=0;j<32;j+=8)
    tile[ty+j][tx] = pb[(size_t)(c0+ty+j)*NPTS + n0+tx];
  __syncthreads();
  float* ob = g_ptsT + (size_t)b*NPTS*DIM;
#pragma unroll
  for (int j=0;j<32;j+=8)
    ob[(size_t)(n0+ty+j)*DIM + c0+tx] = tile[tx][ty+j];
}

// ---------------- build feat [M][68]: norm(3) | pts(64) | 0 ----------------
__global__ void feat_kernel(const float* __restrict__ xyz){
  const int blk = blockIdx.x;                 // b*1024+s
  const int b   = blk >> 10;
  __shared__ int   sn[NS];
  __shared__ float sc[3];
  const int tid = threadIdx.x;
  if (tid<NS) sn[tid]=g_ball[blk*NS+tid];
  if (tid>=32 && tid<35) sc[tid-32]=g_new_xyz[blk*3 + (tid-32)];
  __syncthreads();
  const int c  = tid & 63;
  const int k0 = tid >> 6;
  const size_t mbase = (size_t)blk*NS;
#pragma unroll
  for (int k=k0; k<NS; k+=4){
    int n = sn[k];
    g_feat[(mbase+k)*68 + 3 + c] = g_ptsT[((size_t)b*NPTS + n)*DIM + c];
  }
  if (tid<96){
    int k=tid/3, d=tid%3;
    int n=sn[k];
    g_feat[(mbase+k)*68 + d] =
      __fsub_rn(xyz[(size_t)b*3*NPTS + (size_t)d*NPTS + n], sc[d]);
  }
  if (tid<NS) g_feat[(mbase+tid)*68 + 67] = 0.f;
}

// ---------------- GEMM: h = act(A) @ W^T + bias, f32x2 FFMA2 ---------------
// A: [M][K], W: [BN][wld] row-major, H: [M][BN]
// Epilogue computes deterministic per-block column sum/sumsq -> g_pS/g_pSS.
template<int K, int BN, bool AFF>
__global__ __launch_bounds__(256) void gemm_kernel(const float* __restrict__ A,
    const float* __restrict__ W, int wld,
    const float* __restrict__ bias, float* __restrict__ H){
  extern __shared__ float sm[];
  float* sAT   = sm;                    // [K][68]  (K-major A tile, row=k)
  float* sB    = sAT + K*68;            // [K][BN+4]
  float* sbias = sB + K*(BN+4);         // BN
  float* ssc   = sbias + BN;            // K (AFF only)
  float* ssh   = ssc + K;
  const int tid = threadIdx.x;
  const int m0  = blockIdx.x*64;

  for (int o=tid;o<BN;o+=256) sbias[o]=bias[o];
  if (AFF) for (int cc=tid; cc<K; cc+=256){ ssc[cc]=g_scale[cc]; ssh[cc]=g_shift[cc]; }
  for (int idx=tid; idx<BN*wld; idx+=256){
    int o=idx/wld, cc=idx-o*wld;
    sB[cc*(BN+4)+o]=W[idx];
  }
  if (K>wld) for (int o=tid;o<BN;o+=256) sB[(K-1)*(BN+4)+o]=0.f;
  if (AFF) __syncthreads();

  constexpr int K4 = K/4;
  const float4* A4 = (const float4*)A;
  for (int idx=tid; idx<64*K4; idx+=256){
    int m=idx/K4, c4=idx-m*K4;
    float4 v = A4[(size_t)(m0+m)*K4 + c4];
    if (AFF){
      int cc=c4*4;
      v.x = fmaxf(fmaf(v.x, ssc[cc  ], ssh[cc  ]), 0.f);
      v.y = fmaxf(fmaf(v.y, ssc[cc+1], ssh[cc+1]), 0.f);
      v.z = fmaxf(fmaf(v.z, ssc[cc+2], ssh[cc+2]), 0.f);
      v.w = fmaxf(fmaf(v.w, ssc[cc+3], ssh[cc+3]), 0.f);
    }
    int cc=c4*4;
    sAT[(cc  )*68+m]=v.x;
    sAT[(cc+1)*68+m]=v.y;
    sAT[(cc+2)*68+m]=v.z;
    sAT[(cc+3)*68+m]=v.w;
  }
  __syncthreads();

  constexpr int NPT = BN/16;            // 4 or 8 output cols per thread
  constexpr int NP2 = NPT/2;
  const int tm = tid>>4, tn = tid&15;
  u64 acc[4][NP2];
#pragma unroll
  for (int i=0;i<4;i++)
#pragma unroll
    for (int j=0;j<NP2;j++) acc[i][j]=pack2(sbias[tn*NPT+2*j],sbias[tn*NPT+2*j+1]);

  const float* ApT = sAT + tm*4;
  const float* Bp  = sB + tn*NPT;
#pragma unroll 4
  for (int k=0;k<K;k++){
    float4 av = *(const float4*)(ApT + k*68);
    u64 a0=pack2(av.x,av.x), a1=pack2(av.y,av.y),
        a2=pack2(av.z,av.z), a3=pack2(av.w,av.w);
    u64 b2[NP2];
    const float4* b4 = (const float4*)(Bp + k*(BN+4));
#pragma unroll
    for (int j=0;j<NP2/2;j++){
      float4 t=b4[j];
      b2[2*j]=pack2(t.x,t.y); b2[2*j+1]=pack2(t.z,t.w);
    }
#pragma unroll
    for (int j=0;j<NP2;j++){
      fma2(acc[0][j],a0,b2[j]);
      fma2(acc[1][j],a1,b2[j]);
      fma2(acc[2][j],a2,b2[j]);
      fma2(acc[3][j],a3,b2[j]);
    }
  }

  float vals[4][NPT];
#pragma unroll
  for (int i=0;i<4;i++)
#pragma unroll
    for (int j=0;j<NP2;j++) unpack2(vals[i][2*j], vals[i][2*j+1], acc[i][j]);

#pragma unroll
  for (int i=0;i<4;i++){
    float* outp = H + (size_t)(m0+tm*4+i)*BN + tn*NPT;
#pragma unroll
    for (int j=0;j<NPT/4;j++){
      float4 t; t.x=vals[i][4*j]; t.y=vals[i][4*j+1]; t.z=vals[i][4*j+2]; t.w=vals[i][4*j+3];
      *(float4*)(outp + 4*j) = t;
    }
  }

  // ---- deterministic column sum / sumsq (reuses sAT space) ----
  __syncthreads();                      // everyone done reading sAT/sB
  float* sS  = sm;                      // [BN][16]
  float* sSS = sm + 16*BN;              // [BN][16]
#pragma unroll
  for (int j=0;j<NPT;j++){
    float v0=vals[0][j], v1=vals[1][j], v2=vals[2][j], v3=vals[3][j];
    float s  = ((v0+v1)+v2)+v3;
    float ss = ((v0*v0+v1*v1)+v2*v2)+v3*v3;
    sS [(tn*NPT+j)*16 + tm] = s;
    sSS[(tn*NPT+j)*16 + tm] = ss;
  }
  __syncthreads();
  if (tid < BN){
    float s=0.f, ss=0.f;
#pragma unroll
    for (int t=0;t<16;t++){ s+=sS[tid*16+t]; ss+=sSS[tid*16+t]; }
    g_pS [blockIdx.x*128 + tid] = s;
    g_pSS[blockIdx.x*128 + tid] = ss;
  }
}

// ---------------- reduce 4096 block partials -> 64 -> scale/shift ----------
__global__ void reduce_kernel(){
  int c = threadIdx.x, b = blockIdx.x;
  float s=0.f, ss=0.f;
  for (int j=0;j<64;j++){
    s  += g_pS [(b*64+j)*128 + c];
    ss += g_pSS[(b*64+j)*128 + c];
  }
  g_r1[b*128+c]=s; g_r1[64*128 + b*128+c]=ss;
}

__global__ void finalize_kernel(const float* __restrict__ g, const float* __restrict__ beta){
  const int c = threadIdx.x;
  float s=0.f, ss=0.f;
  for (int i=0;i<64;i++){ s+=g_r1[i*128+c]; ss+=g_r1[64*128+i*128+c]; }
  const float inv = 1.0f/(float)MROWS;
  float mean = s*inv;
  float var  = ss*inv - mean*mean;
  float rstd = rsqrtf(var + 1e-5f);
  float sc   = rstd*g[c];
  g_scale[c] = sc;
  g_shift[c] = beta[c] - mean*sc;
}

// ---------------- layer-3 norm+relu+maxpool + second output ----------------
__global__ void pool_kernel(float* __restrict__ out){
  const int blk=blockIdx.x;                  // b*1024+s
  const int o  =threadIdx.x;                 // 0..127
  const int b=blk>>10, s=blk&1023;
  const float sc=g_scale[o], sh=g_shift[o];
  const float* p = g_h3 + (size_t)blk*NS*128 + o;
  float m=-3.4e38f;
#pragma unroll 8
  for (int k=0;k<NS;k++) m = fmaxf(m, fmaf(p[(size_t)k*128], sc, sh));
  out[24576 + (size_t)b*128*SPTS + (size_t)o*SPTS + s] = fmaxf(m, 0.f);
}

// ---------------- launch ----------------------------------------------------
extern "C" void kernel_launch(void* const* d_in, const int* in_sizes, int n_in,
                              void* d_out, int out_size){
  (void)in_sizes; (void)n_in; (void)out_size;
  const float* xyz = (const float*)d_in[0];
  const float* pts = (const float*)d_in[1];
  const float* w0  = (const float*)d_in[2];
  const float* b0  = (const float*)d_in[3];
  const float* gg0 = (const float*)d_in[4];
  const float* be0 = (const float*)d_in[5];
  const float* w1  = (const float*)d_in[6];
  const float* b1  = (const float*)d_in[7];
  const float* gg1 = (const float*)d_in[8];
  const float* be1 = (const float*)d_in[9];
  const float* w2  = (const float*)d_in[10];
  const float* b2  = (const float*)d_in[11];
  const float* gg2 = (const float*)d_in[12];
  const float* be2 = (const float*)d_in[13];
  float* out = (float*)d_out;

  // smem sizes (floats): K*68 + K*(BN+4) + BN + 2*K
  const int smem1 = (68*68 + 68*68 + 64  + 2*68)*4;   // 37792
  const int smem2 = (64*68 + 64*68 + 64  + 2*64)*4;   // 35584
  const int smem3 = (64*68 + 64*132+ 128 + 2*64)*4;   // 52224

  cudaFuncSetAttribute(fps_kernel, cudaFuncAttributeMaxDynamicSharedMemorySize, 3*NPTS*4);
  cudaFuncSetAttribute((const void*)gemm_kernel<68,64,false>,
                       cudaFuncAttributeMaxDynamicSharedMemorySize, smem1);
  cudaFuncSetAttribute((const void*)gemm_kernel<64,64,true>,
                       cudaFuncAttributeMaxDynamicSharedMemorySize, smem2);
  cudaFuncSetAttribute((const void*)gemm_kernel<64,128,true>,
                       cudaFuncAttributeMaxDynamicSharedMemorySize, smem3);

  float *pFeat,*pH1,*pH2,*pH3;
  cudaGetSymbolAddress((void**)&pFeat, g_feat);
  cudaGetSymbolAddress((void**)&pH1,   g_h1);
  cudaGetSymbolAddress((void**)&pH2,   g_h2);
  cudaGetSymbolAddress((void**)&pH3,   g_h3);

  fps_kernel<<<BATCH, 1024, 3*NPTS*4>>>(xyz);
  newxyz_kernel<<<BATCH, SPTS>>>(xyz, out);
  ball_kernel<<<1024, 256>>>(xyz);
  transpose_kernel<<<dim3(NPTS/32, DIM/32, BATCH), dim3(32,8)>>>(pts);
  feat_kernel<<<BATCH*SPTS, 256>>>(xyz);

  gemm_kernel<68,64,false><<<NBLK, 256, smem1>>>(pFeat, w0, 67, b0, pH1);
  reduce_kernel<<<64, 64>>>();
  finalize_kernel<<<1, 64>>>(gg0, be0);

  gemm_kernel<64,64,true><<<NBLK, 256, smem2>>>(pH1, w1, 64, b1, pH2);
  reduce_kernel<<<64, 64>>>();
  finalize_kernel<<<1, 64>>>(gg1, be1);

  gemm_kernel<64,128,true><<<NBLK, 256, smem3>>>(pH2, w2, 64, b2, pH3);
  reduce_kernel<<<64, 128>>>();
  finalize_kernel<<<1, 128>>>(gg2, be2);

  pool_kernel<<<BATCH*SPTS, 128>>>(out);
}